// round 3
// baseline (speedup 1.0000x reference)
#include <cuda_runtime.h>
#include <cuda_bf16.h>
#include <cstdint>

// ============================================================================
// out[M,N] = X[M,K] @ sign(W)[N,K]^T + bias[N],  M=N=K=4096, fp32.
// Harness PTX target is sm_103 (no 'a') => tcgen05 unavailable.
// Strategy: X -> bf16 hi + bf16 lo, W -> sign(W) in bf16 (exact),
// two mma.sync bf16 passes into fp32 accumulators (rel err ~1e-5).
// Pipelined cp.async mainloop, swizzled SMEM, ldmatrix fragments.
// ============================================================================

static constexpr int MM = 4096;
static constexpr int NN = 4096;
static constexpr int KK = 4096;

static constexpr int BM = 128;
static constexpr int BN = 256;
static constexpr int BK = 64;            // 64 bf16 = 128B row
static constexpr int STAGES = 3;
static constexpr int CHUNKS = KK / BK;   // 64
static constexpr int THREADS = 256;      // 8 warps: 2 (M) x 4 (N), warp tile 64x64

// SMEM stage layout (bytes)
static constexpr int XH_BYTES = BM * 128;          // 16384
static constexpr int XL_BYTES = BM * 128;          // 16384
static constexpr int B_BYTES  = BN * 128;          // 32768
static constexpr int XH_OFF = 0;
static constexpr int XL_OFF = XH_BYTES;
static constexpr int B_OFF  = XH_BYTES + XL_BYTES;
static constexpr int STAGE_BYTES = XH_BYTES + XL_BYTES + B_BYTES;  // 65536
static constexpr int SMEM_TOTAL = STAGES * STAGE_BYTES;            // 196608

// ---------------------------------------------------------------------------
// Scratch (allocation-free)
// ---------------------------------------------------------------------------
__device__ __align__(1024) __nv_bfloat16 g_xh[(size_t)MM * KK];
__device__ __align__(1024) __nv_bfloat16 g_xl[(size_t)MM * KK];
__device__ __align__(1024) __nv_bfloat16 g_wb[(size_t)NN * KK];

// ---------------------------------------------------------------------------
// helpers
// ---------------------------------------------------------------------------
__device__ __forceinline__ uint32_t smem_u32(const void* p) {
    uint32_t a;
    asm("{ .reg .u64 t; cvta.to.shared.u64 t, %1; cvt.u32.u64 %0, t; }"
        : "=r"(a) : "l"(p));
    return a;
}

#define CP_ASYNC_16(dst, src) \
    asm volatile("cp.async.cg.shared.global [%0], [%1], 16;" \
        :: "r"(dst), "l"(src) : "memory")
#define CP_ASYNC_COMMIT() asm volatile("cp.async.commit_group;" ::: "memory")
#define CP_ASYNC_WAIT_1() asm volatile("cp.async.wait_group 1;" ::: "memory")

__device__ __forceinline__ void ldmatrix_x4(uint32_t& r0, uint32_t& r1,
                                            uint32_t& r2, uint32_t& r3,
                                            uint32_t addr) {
    asm volatile("ldmatrix.sync.aligned.m8n8.x4.shared.b16 {%0,%1,%2,%3}, [%4];"
                 : "=r"(r0), "=r"(r1), "=r"(r2), "=r"(r3) : "r"(addr));
}

__device__ __forceinline__ void mma_bf16(float* d, const uint32_t* a,
                                         uint32_t b0, uint32_t b1) {
    asm volatile(
        "mma.sync.aligned.m16n8k16.row.col.f32.bf16.bf16.f32 "
        "{%0,%1,%2,%3}, {%4,%5,%6,%7}, {%8,%9}, {%0,%1,%2,%3};"
        : "+f"(d[0]), "+f"(d[1]), "+f"(d[2]), "+f"(d[3])
        : "r"(a[0]), "r"(a[1]), "r"(a[2]), "r"(a[3]), "r"(b0), "r"(b1));
}

// ---------------------------------------------------------------------------
// Conversion kernels
// ---------------------------------------------------------------------------
__device__ __forceinline__ uint32_t pack2(__nv_bfloat16 a, __nv_bfloat16 b) {
    return ((uint32_t)__bfloat16_as_ushort(b) << 16) | (uint32_t)__bfloat16_as_ushort(a);
}

__global__ void __launch_bounds__(256) convert_x_kernel(
    const float4* __restrict__ x, uint2* __restrict__ xh, uint2* __restrict__ xl) {
    int i = blockIdx.x * 256 + threadIdx.x;
    float4 v = x[i];
    __nv_bfloat16 h0 = __float2bfloat16(v.x);
    __nv_bfloat16 h1 = __float2bfloat16(v.y);
    __nv_bfloat16 h2 = __float2bfloat16(v.z);
    __nv_bfloat16 h3 = __float2bfloat16(v.w);
    __nv_bfloat16 l0 = __float2bfloat16(v.x - __bfloat162float(h0));
    __nv_bfloat16 l1 = __float2bfloat16(v.y - __bfloat162float(h1));
    __nv_bfloat16 l2 = __float2bfloat16(v.z - __bfloat162float(h2));
    __nv_bfloat16 l3 = __float2bfloat16(v.w - __bfloat162float(h3));
    uint2 ph; ph.x = pack2(h0, h1); ph.y = pack2(h2, h3);
    uint2 pl; pl.x = pack2(l0, l1); pl.y = pack2(l2, l3);
    xh[i] = ph;
    xl[i] = pl;
}

__global__ void __launch_bounds__(256) convert_w_kernel(
    const float4* __restrict__ w, uint2* __restrict__ wb) {
    int i = blockIdx.x * 256 + threadIdx.x;
    float4 v = w[i];
    float s0 = (v.x > 0.f) ? 1.f : ((v.x < 0.f) ? -1.f : 0.f);
    float s1 = (v.y > 0.f) ? 1.f : ((v.y < 0.f) ? -1.f : 0.f);
    float s2 = (v.z > 0.f) ? 1.f : ((v.z < 0.f) ? -1.f : 0.f);
    float s3 = (v.w > 0.f) ? 1.f : ((v.w < 0.f) ? -1.f : 0.f);
    uint2 p;
    p.x = pack2(__float2bfloat16(s0), __float2bfloat16(s1));
    p.y = pack2(__float2bfloat16(s2), __float2bfloat16(s3));
    wb[i] = p;
}

// ---------------------------------------------------------------------------
// GEMM kernel
// ---------------------------------------------------------------------------
__global__ void __launch_bounds__(THREADS, 1)
bingemm_kernel(const __nv_bfloat16* __restrict__ xh,
               const __nv_bfloat16* __restrict__ xl,
               const __nv_bfloat16* __restrict__ wb,
               const float* __restrict__ bias,
               float* __restrict__ out) {
    extern __shared__ __align__(1024) char smem[];
    const uint32_t sb = smem_u32(smem);

    const int tid = threadIdx.x;
    const int wid = tid >> 5;
    const int lane = tid & 31;
    const int warp_m = wid & 1;    // 0..1
    const int warp_n = wid >> 1;   // 0..3
    const int m0 = blockIdx.y * BM;
    const int n0 = blockIdx.x * BN;

    // --- cp.async tile loader ---
    // Each stage: A_hi (128 rows), A_lo (128 rows), B (256 rows); row = 128B = 8 chunks.
    // thread t covers (row = i*32 + t/8, chunk = t%7..) ; swizzle chunk ^= row&7.
    const int ld_row = tid >> 3;         // 0..31
    const int ld_chunk = tid & 7;        // 0..7

    auto load_stage = [&](int stage, int c) {
        const uint32_t sbase = sb + stage * STAGE_BYTES;
        const int k0 = c * BK;
        #pragma unroll
        for (int i = 0; i < 4; i++) {
            int row = i * 32 + ld_row;
            uint32_t soff = row * 128 + ((ld_chunk ^ (row & 7)) << 4);
            const __nv_bfloat16* src = xh + (size_t)(m0 + row) * KK + k0 + ld_chunk * 8;
            CP_ASYNC_16(sbase + XH_OFF + soff, src);
        }
        #pragma unroll
        for (int i = 0; i < 4; i++) {
            int row = i * 32 + ld_row;
            uint32_t soff = row * 128 + ((ld_chunk ^ (row & 7)) << 4);
            const __nv_bfloat16* src = xl + (size_t)(m0 + row) * KK + k0 + ld_chunk * 8;
            CP_ASYNC_16(sbase + XL_OFF + soff, src);
        }
        #pragma unroll
        for (int i = 0; i < 8; i++) {
            int row = i * 32 + ld_row;
            uint32_t soff = row * 128 + ((ld_chunk ^ (row & 7)) << 4);
            const __nv_bfloat16* src = wb + (size_t)(n0 + row) * KK + k0 + ld_chunk * 8;
            CP_ASYNC_16(sbase + B_OFF + soff, src);
        }
    };

    // prologue
    load_stage(0, 0); CP_ASYNC_COMMIT();
    load_stage(1, 1); CP_ASYNC_COMMIT();

    // --- ldmatrix per-thread address components ---
    const int mt = lane >> 3;            // matrix index 0..3
    const int lrow = lane & 7;
    // A: mat0=(m+0,k+0) mat1=(m+8,k+0) mat2=(m+0,k+8) mat3=(m+8,k+8)
    const int a_row = warp_m * 64 + lrow + ((mt & 1) << 3);   // + mi*16
    const int a_koff = mt >> 1;                               // 8-elem chunk offset
    // B: mat0=(n+0,k+0) mat1=(n+0,k+8) mat2=(n+8,k+0) mat3=(n+8,k+8)
    const int b_row = warp_n * 64 + lrow + ((mt >> 1) << 3);  // + nj2*16
    const int b_koff = mt & 1;

    float acc[4][8][4];
    #pragma unroll
    for (int mi = 0; mi < 4; mi++)
        #pragma unroll
        for (int nj = 0; nj < 8; nj++)
            #pragma unroll
            for (int q = 0; q < 4; q++) acc[mi][nj][q] = 0.f;

    for (int c = 0; c < CHUNKS; c++) {
        CP_ASYNC_WAIT_1();
        __syncthreads();
        if (c + 2 < CHUNKS) load_stage((c + 2) % STAGES, c + 2);
        CP_ASYNC_COMMIT();

        const uint32_t sbase = sb + (c % STAGES) * STAGE_BYTES;

        #pragma unroll
        for (int ks = 0; ks < 4; ks++) {
            // load A fragments (hi + lo), 4 m-slices each
            uint32_t ah[4][4], al[4][4];
            #pragma unroll
            for (int mi = 0; mi < 4; mi++) {
                int row = a_row + mi * 16;
                int kch = ks * 2 + a_koff;
                uint32_t off = row * 128 + ((kch ^ (row & 7)) << 4);
                ldmatrix_x4(ah[mi][0], ah[mi][1], ah[mi][2], ah[mi][3],
                            sbase + XH_OFF + off);
                ldmatrix_x4(al[mi][0], al[mi][1], al[mi][2], al[mi][3],
                            sbase + XL_OFF + off);
            }
            // B: 4 x ldmatrix.x4, each covers two n8 slices
            #pragma unroll
            for (int nj2 = 0; nj2 < 4; nj2++) {
                int row = b_row + nj2 * 16;
                int kch = ks * 2 + b_koff;
                uint32_t off = row * 128 + ((kch ^ (row & 7)) << 4);
                uint32_t b0, b1, b2, b3;
                ldmatrix_x4(b0, b1, b2, b3, sbase + B_OFF + off);
                #pragma unroll
                for (int mi = 0; mi < 4; mi++) {
                    mma_bf16(acc[mi][nj2 * 2 + 0], ah[mi], b0, b1);
                    mma_bf16(acc[mi][nj2 * 2 + 1], ah[mi], b2, b3);
                    mma_bf16(acc[mi][nj2 * 2 + 0], al[mi], b0, b1);
                    mma_bf16(acc[mi][nj2 * 2 + 1], al[mi], b2, b3);
                }
            }
        }
        __syncthreads();
    }

    // --- epilogue: += bias, write fp32 ---
    const int qcol = (lane & 3) * 2;
    float2 bv[8];
    #pragma unroll
    for (int nj = 0; nj < 8; nj++) {
        bv[nj] = *reinterpret_cast<const float2*>(
            bias + n0 + warp_n * 64 + nj * 8 + qcol);
    }

    #pragma unroll
    for (int mi = 0; mi < 4; mi++) {
        int r0 = m0 + warp_m * 64 + mi * 16 + (lane >> 2);
        int r1 = r0 + 8;
        float* p0 = out + (size_t)r0 * NN + n0 + warp_n * 64 + qcol;
        float* p1 = out + (size_t)r1 * NN + n0 + warp_n * 64 + qcol;
        #pragma unroll
        for (int nj = 0; nj < 8; nj++) {
            float2 v0, v1;
            v0.x = acc[mi][nj][0] + bv[nj].x;
            v0.y = acc[mi][nj][1] + bv[nj].y;
            v1.x = acc[mi][nj][2] + bv[nj].x;
            v1.y = acc[mi][nj][3] + bv[nj].y;
            *reinterpret_cast<float2*>(p0 + nj * 8) = v0;
            *reinterpret_cast<float2*>(p1 + nj * 8) = v1;
        }
    }
}

// ---------------------------------------------------------------------------
// Host launch
// ---------------------------------------------------------------------------
extern "C" void kernel_launch(void* const* d_in, const int* in_sizes, int n_in,
                              void* d_out, int out_size) {
    const float* x    = (const float*)d_in[0];
    const float* w    = (const float*)d_in[1];
    const float* bias = (const float*)d_in[2];
    float* out = (float*)d_out;

    void *p_xh = nullptr, *p_xl = nullptr, *p_wb = nullptr;
    cudaGetSymbolAddress(&p_xh, g_xh);
    cudaGetSymbolAddress(&p_xl, g_xl);
    cudaGetSymbolAddress(&p_wb, g_wb);

    const int n4 = MM * KK / 4;
    convert_x_kernel<<<n4 / 256, 256>>>((const float4*)x, (uint2*)p_xh, (uint2*)p_xl);
    convert_w_kernel<<<n4 / 256, 256>>>((const float4*)w, (uint2*)p_wb);

    static bool attr_set = false;
    if (!attr_set) {
        cudaFuncSetAttribute(bingemm_kernel,
                             cudaFuncAttributeMaxDynamicSharedMemorySize, SMEM_TOTAL);
        attr_set = true;
    }

    dim3 grid(NN / BN, MM / BM);  // (16, 32)
    bingemm_kernel<<<grid, THREADS, SMEM_TOTAL>>>(
        (const __nv_bfloat16*)p_xh, (const __nv_bfloat16*)p_xl,
        (const __nv_bfloat16*)p_wb, bias, out);
}